// round 3
// baseline (speedup 1.0000x reference)
#include <cuda_runtime.h>
#include <cuda_bf16.h>

#define BB 8
#define KN 512
#define QN 128
#define DD 256      // DK = DQ = DV = H = 256
#define NEGC (-1000000.0f)
#define QT 4

// scratch: rows [0,1024) = q_proj (B*Q), rows [1024,5120) = k_proj (B*K)
__device__ float g_proj[(BB * QN + BB * KN) * DD];

__device__ __forceinline__ float fast_tanh(float x) {
    float y;
    asm("tanh.approx.f32 %0, %1;" : "=f"(y) : "f"(x));
    return y;
}

// ---------------------------------------------------------------------------
// Kernel 1: fused projection GEMM.
// out[m][h] = sum_d A[m][d] * W_hidden[h][off + d]
//   m <  1024 : A = queries row m,        off = 0   (Wq)
//   m >= 1024 : A = keys row (m - 1024), off = 256 (Wk)
// BM=64, BN=64, BK=16, 256 threads, 4x4 micro-tile.
// ---------------------------------------------------------------------------
__global__ __launch_bounds__(256) void proj_kernel(
    const float* __restrict__ queries,
    const float* __restrict__ keys,
    const float* __restrict__ W_hidden)
{
    __shared__ float As[16][68];   // pad to 68: conflict-free, rows 16B-aligned
    __shared__ float Bs[16][68];

    const int m0 = blockIdx.x * 64;
    const int n0 = blockIdx.y * 64;
    const bool isQ = (m0 < BB * QN);
    const float* A = isQ ? (queries + m0 * DD) : (keys + (m0 - BB * QN) * DD);
    const int off = isQ ? 0 : DD;

    const int tid = threadIdx.x;
    const int tx = tid & 15;       // n direction (16 * 4 = 64)
    const int ty = tid >> 4;       // m direction (16 * 4 = 64)

    float acc[4][4] = {};

    for (int kb = 0; kb < DD; kb += 16) {
        #pragma unroll
        for (int i = 0; i < 4; i++) {
            int f = tid + i * 256;
            int m = f >> 4, kk = f & 15;
            As[kk][m] = A[m * DD + kb + kk];
        }
        #pragma unroll
        for (int i = 0; i < 4; i++) {
            int f = tid + i * 256;
            int n = f >> 4, kk = f & 15;
            Bs[kk][n] = W_hidden[(n0 + n) * (2 * DD) + off + kb + kk];
        }
        __syncthreads();
        #pragma unroll
        for (int kk = 0; kk < 16; kk++) {
            float a[4], b[4];
            #pragma unroll
            for (int i = 0; i < 4; i++) a[i] = As[kk][ty * 4 + i];
            #pragma unroll
            for (int j = 0; j < 4; j++) b[j] = Bs[kk][tx * 4 + j];
            #pragma unroll
            for (int i = 0; i < 4; i++)
                #pragma unroll
                for (int j = 0; j < 4; j++)
                    acc[i][j] += a[i] * b[j];
        }
        __syncthreads();
    }

    #pragma unroll
    for (int i = 0; i < 4; i++) {
        int m = m0 + ty * 4 + i;
        #pragma unroll
        for (int j = 0; j < 4; j++)
            g_proj[m * DD + n0 + tx * 4 + j] = acc[i][j];
    }
}

// ---------------------------------------------------------------------------
// Kernel 2: fused logits (tanh-MUFU) + masked softmax + output GEMV.
// One block = (b, 4 consecutive queries). 256 threads.
// ---------------------------------------------------------------------------
__global__ __launch_bounds__(256, 2) void attn_kernel(
    const float* __restrict__ values,
    const void*  __restrict__ valid_len,
    const float* __restrict__ W_score,
    float*       __restrict__ out)
{
    __shared__ float qp[QT][DD];
    __shared__ float sl[QT][KN];
    __shared__ float ws[DD];
    __shared__ float red[9];

    const int tid = threadIdx.x;
    const int b  = blockIdx.x >> 5;            // Q/QT = 32 blocks per batch
    const int q0 = (blockIdx.x & 31) * QT;

    ws[tid] = W_score[tid];
    #pragma unroll
    for (int j = 0; j < QT; j++)
        qp[j][tid] = g_proj[(b * QN + q0 + j) * DD + tid];

    // valid_len dtype auto-detect: jnp int64 stores zero high words (values < 512)
    int vl;
    {
        const int* w32 = (const int*)valid_len;
        bool is64 = ((w32[1] | w32[3] | w32[5] | w32[7]) == 0);
        vl = is64 ? (int)(((const long long*)valid_len)[b]) : w32[b];
    }
    __syncthreads();

    // ---- logits: thread owns k = tid and k = tid + 256, all 4 queries ----
    #pragma unroll
    for (int rep = 0; rep < 2; rep++) {
        const int k = tid + rep * 256;
        const float* kp = &g_proj[(BB * QN + b * KN + k) * DD];
        float acc[QT] = {};
        #pragma unroll 4
        for (int h = 0; h < DD; h += 4) {
            float4 kv = *(const float4*)(kp + h);
            float4 wv = *(const float4*)(&ws[h]);
            #pragma unroll
            for (int j = 0; j < QT; j++) {
                float4 qv = *(const float4*)(&qp[j][h]);
                acc[j] += wv.x * fast_tanh(qv.x + kv.x);
                acc[j] += wv.y * fast_tanh(qv.y + kv.y);
                acc[j] += wv.z * fast_tanh(qv.z + kv.z);
                acc[j] += wv.w * fast_tanh(qv.w + kv.w);
            }
        }
        const bool valid = (k < vl);
        #pragma unroll
        for (int j = 0; j < QT; j++)
            sl[j][k] = valid ? acc[j] : NEGC;
    }
    __syncthreads();

    // ---- softmax per query (exactly mirrors reference: NEG-masked softmax) ----
    #pragma unroll
    for (int j = 0; j < QT; j++) {
        float a = sl[j][tid];
        float c = sl[j][tid + 256];
        float m = fmaxf(a, c);
        #pragma unroll
        for (int o = 16; o; o >>= 1)
            m = fmaxf(m, __shfl_xor_sync(0xFFFFFFFFu, m, o));
        if ((tid & 31) == 0) red[tid >> 5] = m;
        __syncthreads();
        if (tid == 0) {
            float mm = red[0];
            #pragma unroll
            for (int i = 1; i < 8; i++) mm = fmaxf(mm, red[i]);
            red[8] = mm;
        }
        __syncthreads();
        m = red[8];
        float e0 = __expf(a - m);
        float e1 = __expf(c - m);
        float s = e0 + e1;
        #pragma unroll
        for (int o = 16; o; o >>= 1)
            s += __shfl_xor_sync(0xFFFFFFFFu, s, o);
        if ((tid & 31) == 0) red[tid >> 5] = s;
        __syncthreads();
        if (tid == 0) {
            float ss = 0.f;
            #pragma unroll
            for (int i = 0; i < 8; i++) ss += red[i];
            red[8] = ss;
        }
        __syncthreads();
        float inv = 1.0f / red[8];
        sl[j][tid]       = e0 * inv;
        sl[j][tid + 256] = e1 * inv;
        __syncthreads();
    }

    // ---- output GEMV: thread owns output channel v = tid for all 4 queries ----
    const float* vals = values + b * KN * DD;
    float o[QT] = {};
    for (int k4 = 0; k4 < KN / 4; k4++) {
        float aw[QT][4];
        #pragma unroll
        for (int q = 0; q < QT; q++)
            *(float4*)aw[q] = *(const float4*)&sl[q][k4 * 4];
        #pragma unroll
        for (int j = 0; j < 4; j++) {
            float av = vals[(k4 * 4 + j) * DD + tid];
            #pragma unroll
            for (int q = 0; q < QT; q++)
                o[q] += aw[q][j] * av;
        }
    }
    #pragma unroll
    for (int q = 0; q < QT; q++)
        out[(b * QN + q0 + q) * DD + tid] = o[q];
}

extern "C" void kernel_launch(void* const* d_in, const int* in_sizes, int n_in,
                              void* d_out, int out_size)
{
    const float* keys     = (const float*)d_in[0];   // [8, 512, 256]
    const float* values   = (const float*)d_in[1];   // [8, 512, 256]
    const float* queries  = (const float*)d_in[2];   // [8, 128, 256]
    const void*  valid    = d_in[3];                 // [8] int32 or int64
    const float* W_hidden = (const float*)d_in[4];   // [256, 512]
    const float* W_score  = (const float*)d_in[5];   // [256]
    float* out = (float*)d_out;                      // [8, 128, 256]

    dim3 g1(80, 4);                                  // (5120/64, 256/64)
    proj_kernel<<<g1, 256>>>(queries, keys, W_hidden);
    attn_kernel<<<BB * (QN / QT), 256>>>(values, valid, W_score, out);
}